// round 15
// baseline (speedup 1.0000x reference)
#include <cuda_runtime.h>

#define Bsz   128
#define Lseq  4096
#define Hd    64
#define G3    192
#define IN2H  128
#define NCLS  230
#define BL    (Bsz * Lseq)
#define CH    8              // steps per chunk
#define NCH   (Lseq / CH)    // 512 chunks

typedef unsigned long long ull;

// Scratch (allocation-free rule): double-buffered layer outputs.
__device__ float g_bufA[(size_t)BL * IN2H];   // ~268 MB
__device__ float g_bufB[(size_t)BL * IN2H];   // ~268 MB

// ---- dynamic smem layout (bytes) ----
#define W_OFF    0                    // [2][192] rows of 512B, rotate-swizzled
#define W_BYTES  (2 * 192 * 512)      // 196608
#define RING_OFF (W_OFF + W_BYTES)    // [slot2][dir2][CH][192] floats
#define RING_BYTES (2 * 2 * CH * 192 * 4)  // 24576
#define INP_OFF  (RING_OFF + RING_BYTES)   // [dir2][CH][128] floats
#define INP_BYTES (2 * CH * 128 * 4)       // 8192
#define H_OFF    (INP_OFF + INP_BYTES)     // [dir2][parity2][64] floats
#define H_BYTES  (2 * 2 * Hd * 4)          // 1024
#define SMEM_TOTAL (H_OFF + H_BYTES)       // 230400

// ---------------- helpers ----------------
__device__ __forceinline__ ull fma2(ull a, ull b, ull c) {
    ull d;
    asm("fma.rn.f32x2 %0, %1, %2, %3;" : "=l"(d) : "l"(a), "l"(b), "l"(c));
    return d;
}
__device__ __forceinline__ float2 u2f2(ull v) {
    float2 f;
    asm("mov.b64 {%0, %1}, %2;" : "=f"(f.x), "=f"(f.y) : "l"(v));
    return f;
}
__device__ __forceinline__ float tanh_fast(float x) {
    float y;
    asm("tanh.approx.f32 %0, %1;" : "=f"(y) : "f"(x));
    return y;
}
__device__ __forceinline__ float sigm_fast(float x) {
    return fmaf(0.5f, tanh_fast(0.5f * x), 0.5f);
}
__device__ __forceinline__ unsigned smem_u32(const void* p) {
    return (unsigned)__cvta_generic_to_shared(p);
}
__device__ __forceinline__ void cp_async16(unsigned dst, const void* src) {
    asm volatile("cp.async.cg.shared.global [%0], [%1], 16;"
                 :: "r"(dst), "l"(src));
}
__device__ __forceinline__ void cp_commit() {
    asm volatile("cp.async.commit_group;");
}
template <int N>
__device__ __forceinline__ void cp_wait() {
    asm volatile("cp.async.wait_group %0;" :: "n"(N));
}

// ---------------- fused scan + gx kernel ----------------
// Block = one batch element, 384 threads:
//   tid 0..255   : scan (R11 core). d = tid>>7, j = (tid&127)>>1, half = tid&1.
//   tid 256..383 : gx helpers. Compute next chunk's gx (both dirs) from the
//                  PREVIOUS layer's output (inp_g) with w_ih resident in smem.
// Handoff: 2-slot gx ring, one __syncthreads per 8-step chunk.
__global__ void __launch_bounds__(384)
scan_kernel(const float* __restrict__ w_hh,
            const float* __restrict__ b_hh,
            const float* __restrict__ x,
            const float* __restrict__ w_ih0,
            const float* __restrict__ b_ih,
            const float* __restrict__ w_ih,
            const float* __restrict__ inp_g,   // prev layer output (layer>0)
            float* __restrict__ out_g,         // this layer output
            int layer) {
    extern __shared__ __align__(16) char smem_dyn[];
    const int b = blockIdx.x;
    const int tid = threadIdx.x;

    float* h_base = (float*)(smem_dyn + H_OFF);
    float* ring_base = (float*)(smem_dyn + RING_OFF);

    // ---------------- W smem fill (all 384 threads, layer>0) --------------
    if (layer > 0) {
        const char* wsrc =
            (const char*)(w_ih + ((size_t)(layer - 1) * 2) * G3 * IN2H);
#pragma unroll 4
        for (int i = 0; i < 32; i++) {
            int idx = tid + i * 384;     // 0..12287
            int dc = idx >> 5;           // 0..383  (= d*192 + c)
            int q = idx & 31;            // granule within row
            int c = (dc >= 192) ? (dc - 192) : dc;
            int pos = (q + c) & 31;      // rotate swizzle
            cp_async16(smem_u32(smem_dyn + W_OFF + dc * 512 + pos * 16),
                       wsrc + (size_t)dc * 512 + q * 16);
        }
        cp_commit();
        cp_wait<0>();
    }
    __syncthreads();   // barrier A

    if (tid < 256) {
        // =================== SCANNER ===================
        const int d = tid >> 7;
        const int lt = tid & 127;
        const int j = lt >> 1;
        const int half = lt & 1;
        const unsigned barid = 1 + d;

        const size_t base = ((size_t)layer * 2 + d) * G3;
        const ull* Wr = (const ull*)w_hh + (base + j) * 32 + half * 16;
        const ull* Wz = (const ull*)w_hh + (base + 64 + j) * 32 + half * 16;
        const ull* Wn = (const ull*)w_hh + (base + 128 + j) * 32 + half * 16;
        ull wr[16], wz[16], wn[16];
#pragma unroll
        for (int i = 0; i < 16; i++) {
            wr[i] = Wr[i]; wz[i] = Wz[i]; wn[i] = Wn[i];
        }
        const float br = b_hh[base + j];
        const float bz = b_hh[base + 64 + j];
        const float bn = b_hh[base + 128 + j];

        if (lt < Hd) h_base[(d * 2 + 0) * Hd + lt] = 0.0f;
        float hreg = 0.0f;

        const int t0 = (d == 0) ? 0 : (Lseq - 1);
        const int tstep = (d == 0) ? 1 : -1;

        // layer-0 x feed (depth-2 prefetch, static scalars)
        float w0r = 0.f, w0z = 0.f, w0n = 0.f;
        float c0r = 0.f, c0z = 0.f, c0n = 0.f;
        const float* xs = nullptr;
        float qr0 = 0.f, qr1 = 0.f;
        if (layer == 0) {
            if (half == 0) {
                w0r = w_ih0[d * G3 + j];
                w0z = w_ih0[d * G3 + 64 + j];
                w0n = w_ih0[d * G3 + 128 + j];
                c0r = b_ih[(size_t)d * G3 + j];
                c0z = b_ih[(size_t)d * G3 + 64 + j];
                c0n = b_ih[(size_t)d * G3 + 128 + j];
            }
            xs = x + (size_t)b * Lseq + t0;
            if (half == 0) { qr0 = xs[0]; qr1 = xs[(long)tstep]; }
        }
        float* outp = out_g + (size_t)b * Lseq * IN2H + d * Hd + j;

        __syncthreads();   // barrier B (helpers produced chunk 0)

#define SCAN_STEP(PR, S)                                                      \
    {                                                                         \
        const int s_ = (S);                                                   \
        float gxr = 0.f, gxz = 0.f, gxn = 0.f;                                \
        if (half == 0) {                                                      \
            if (layer == 0) {                                                 \
                float rawr = qr##PR;                                          \
                const int sp_ = s_ + 2;                                       \
                if (sp_ < Lseq) qr##PR = xs[(long)sp_ * tstep];               \
                gxr = fmaf(rawr, w0r, c0r);                                   \
                gxz = fmaf(rawr, w0z, c0z);                                   \
                gxn = fmaf(rawr, w0n, c0n);                                   \
            } else {                                                          \
                const float* rr = ring_base +                                 \
                    ((((s_ >> 3) & 1) * 2 + d) * CH + (s_ & 7)) * G3;         \
                gxr = rr[j];                                                  \
                gxz = rr[64 + j];                                             \
                gxn = rr[128 + j];                                            \
            }                                                                 \
        }                                                                     \
        const ulonglong2* h4_ = (const ulonglong2*)                           \
            (h_base + (d * 2 + (PR)) * Hd + half * 32);                       \
        ull r0 = 0, r1 = 0, z0 = 0, z1 = 0, n0 = 0, n1 = 0;                   \
        _Pragma("unroll")                                                     \
        for (int i = 0; i < 4; i++) {                                         \
            ulonglong2 u = h4_[2 * i];                                        \
            ulonglong2 v = h4_[2 * i + 1];                                    \
            r0 = fma2(wr[4 * i + 0], u.x, r0);                                \
            r1 = fma2(wr[4 * i + 1], u.y, r1);                                \
            z0 = fma2(wz[4 * i + 0], u.x, z0);                                \
            z1 = fma2(wz[4 * i + 1], u.y, z1);                                \
            n0 = fma2(wn[4 * i + 0], u.x, n0);                                \
            n1 = fma2(wn[4 * i + 1], u.y, n1);                                \
            r0 = fma2(wr[4 * i + 2], v.x, r0);                                \
            r1 = fma2(wr[4 * i + 3], v.y, r1);                                \
            z0 = fma2(wz[4 * i + 2], v.x, z0);                                \
            z1 = fma2(wz[4 * i + 3], v.y, z1);                                \
            n0 = fma2(wn[4 * i + 2], v.x, n0);                                \
            n1 = fma2(wn[4 * i + 3], v.y, n1);                                \
        }                                                                     \
        float2 fr0 = u2f2(r0), fr1 = u2f2(r1);                                \
        float2 fz0 = u2f2(z0), fz1 = u2f2(z1);                                \
        float2 fn0 = u2f2(n0), fn1 = u2f2(n1);                                \
        float pgr = (fr0.x + fr0.y) + (fr1.x + fr1.y);                        \
        float pgz = (fz0.x + fz0.y) + (fz1.x + fz1.y);                        \
        float pgn = (fn0.x + fn0.y) + (fn1.x + fn1.y);                        \
        pgr += __shfl_xor_sync(0xFFFFFFFFu, pgr, 1);                          \
        pgz += __shfl_xor_sync(0xFFFFFFFFu, pgz, 1);                          \
        pgn += __shfl_xor_sync(0xFFFFFFFFu, pgn, 1);                          \
        if (half == 0) {                                                      \
            float r_ = sigm_fast(gxr + pgr + br);                             \
            float z_ = sigm_fast(gxz + pgz + bz);                             \
            float n_ = tanh_fast(fmaf(r_, pgn + bn, gxn));                    \
            float hn = fmaf(z_, hreg - n_, n_);                               \
            hreg = hn;                                                        \
            h_base[(d * 2 + (1 - (PR))) * Hd + j] = hn;                       \
            outp[(size_t)(t0 + s_ * tstep) * IN2H] = hn;                      \
        }                                                                     \
        asm volatile("bar.sync %0, %1;" :: "r"(barid), "r"(128) : "memory");  \
    }

#pragma unroll 1
        for (int c = 0; c < NCH; c++) {
#pragma unroll 1
            for (int ss = 0; ss < CH / 2; ss++) {
                const int sb = c * CH + ss * 2;
                SCAN_STEP(0, sb)
                SCAN_STEP(1, sb + 1)
            }
            __syncthreads();   // chunk handoff
        }
#undef SCAN_STEP
    } else {
        // =================== GX HELPERS (128 threads) ===================
        const int ht = tid - 256;
        const int dH = ht & 1;        // this thread's direction
        const int c0 = ht >> 1;       // cols c0, c0+64, c0+128
        // inp loader role: 16 rows = [d][trow]
        const int r16 = ht >> 3;      // 0..15
        const int lane8 = ht & 7;

        float bias_m[3];
        if (layer > 0) {
#pragma unroll
            for (int m = 0; m < 3; m++)
                bias_m[m] = b_ih[((size_t)layer * 2 + dH) * G3 + c0 + 64 * m];
        }

        const char* wb = smem_dyn + W_OFF + (size_t)dH * 192 * 512;
        const char* ib = smem_dyn + INP_OFF + (size_t)dH * CH * 512;

        // one chunk of gx for both dirs (this thread: its dir, 3 cols, 8 t)
        auto do_chunk = [&](int cc) {
            // stage inp rows for this chunk
            {
                int dI = r16 >> 3, trow = r16 & 7;
                int t = (dI == 0) ? (cc * CH + trow)
                                  : (Lseq - 1 - (cc * CH + trow));
                const char* src = (const char*)(inp_g +
                    ((size_t)b * Lseq + t) * IN2H) + lane8 * 64;
                unsigned dst = smem_u32(smem_dyn + INP_OFF + r16 * 512) +
                               lane8 * 64;
#pragma unroll
                for (int u = 0; u < 4; u++)
                    cp_async16(dst + u * 16, src + u * 16);
                cp_commit();
                cp_wait<0>();
                asm volatile("bar.sync 3, 128;" ::: "memory");
            }
            const int slot = cc & 1;
            ull acc[8][3];
#pragma unroll
            for (int t = 0; t < 8; t++)
#pragma unroll
                for (int m = 0; m < 3; m++) acc[t][m] = 0ULL;

#pragma unroll 2
            for (int k8 = 0; k8 < 16; k8++) {
                ulonglong2 ip[8][2];
#pragma unroll
                for (int t = 0; t < 8; t++) {
                    ip[t][0] = *(const ulonglong2*)(ib + t * 512 + k8 * 32);
                    ip[t][1] = *(const ulonglong2*)(ib + t * 512 + k8 * 32 + 16);
                }
#pragma unroll
                for (int m = 0; m < 3; m++) {
                    int c = c0 + 64 * m;
                    int p0 = (2 * k8 + c) & 31;
                    int p1 = (2 * k8 + 1 + c) & 31;
                    ulonglong2 w0v = *(const ulonglong2*)(wb + c * 512 + p0 * 16);
                    ulonglong2 w1v = *(const ulonglong2*)(wb + c * 512 + p1 * 16);
#pragma unroll
                    for (int t = 0; t < 8; t++) {
                        acc[t][m] = fma2(w0v.x, ip[t][0].x, acc[t][m]);
                        acc[t][m] = fma2(w0v.y, ip[t][0].y, acc[t][m]);
                        acc[t][m] = fma2(w1v.x, ip[t][1].x, acc[t][m]);
                        acc[t][m] = fma2(w1v.y, ip[t][1].y, acc[t][m]);
                    }
                }
            }
            float* rb = ring_base + ((slot * 2 + dH) * CH) * G3;
#pragma unroll
            for (int t = 0; t < 8; t++)
#pragma unroll
                for (int m = 0; m < 3; m++) {
                    float2 f = u2f2(acc[t][m]);
                    rb[t * G3 + c0 + 64 * m] = f.x + f.y + bias_m[m];
                }
        };

        // prologue: produce chunk 0
        if (layer > 0) do_chunk(0);
        __syncthreads();   // barrier B

#pragma unroll 1
        for (int c = 0; c < NCH; c++) {
            if (layer > 0 && c + 1 < NCH) do_chunk(c + 1);
            __syncthreads();   // chunk handoff
        }
    }
}

// ---------------- final FC on last timestep ----------------
__global__ void fc_kernel(const float* __restrict__ fc_w,
                          const float* __restrict__ fc_b,
                          const float* __restrict__ hbuf,
                          float* __restrict__ out) {
    int b = blockIdx.x;
    int c = threadIdx.x;
    __shared__ float last[IN2H];
    if (threadIdx.x < IN2H)
        last[threadIdx.x] =
            hbuf[((size_t)b * Lseq + (Lseq - 1)) * IN2H + threadIdx.x];
    __syncthreads();
    if (c < NCLS) {
        float s = fc_b[c];
        const float* w = fc_w + (size_t)c * IN2H;
#pragma unroll 8
        for (int k = 0; k < IN2H; k++) s += last[k] * w[k];
        out[(size_t)b * NCLS + c] = s;
    }
}

extern "C" void kernel_launch(void* const* d_in, const int* in_sizes, int n_in,
                              void* d_out, int out_size) {
    const float* x     = (const float*)d_in[0];
    const float* w_ih0 = (const float*)d_in[1];
    const float* w_ih  = (const float*)d_in[2];
    const float* w_hh  = (const float*)d_in[3];
    const float* b_ih  = (const float*)d_in[4];
    const float* b_hh  = (const float*)d_in[5];
    const float* fc_w  = (const float*)d_in[6];
    const float* fc_b  = (const float*)d_in[7];
    float* out = (float*)d_out;

    cudaFuncSetAttribute(scan_kernel,
                         cudaFuncAttributeMaxDynamicSharedMemorySize,
                         SMEM_TOTAL);

    float* bufA;
    float* bufB;
    cudaGetSymbolAddress((void**)&bufA, g_bufA);
    cudaGetSymbolAddress((void**)&bufB, g_bufB);

    // layer 0: x -> bufA  (gx fused from x; helpers idle)
    scan_kernel<<<Bsz, 384, SMEM_TOTAL>>>(
        w_hh, b_hh, x, w_ih0, b_ih, w_ih, nullptr, bufA, 0);
    // layer 1: bufA -> bufB
    scan_kernel<<<Bsz, 384, SMEM_TOTAL>>>(
        w_hh, b_hh, x, w_ih0, b_ih, w_ih, bufA, bufB, 1);
    // layer 2: bufB -> bufA
    scan_kernel<<<Bsz, 384, SMEM_TOTAL>>>(
        w_hh, b_hh, x, w_ih0, b_ih, w_ih, bufB, bufA, 2);
    // layer 3: bufA -> bufB
    scan_kernel<<<Bsz, 384, SMEM_TOTAL>>>(
        w_hh, b_hh, x, w_ih0, b_ih, w_ih, bufA, bufB, 3);

    fc_kernel<<<Bsz, 256>>>(fc_w, fc_b, bufB, out);
}